// round 1
// baseline (speedup 1.0000x reference)
#include <cuda_runtime.h>
#include <math.h>

#define B_      8
#define N_      1024
#define H_      1024
#define HEADS_  16
#define DH_     64
#define M_      (B_ * N_)        // 8192
#define CTXN_   ((size_t)M_ * H_)  // 8388608

// -------- scratch (device globals; no allocation allowed) --------
__device__ float g_Q[(size_t)B_ * HEADS_ * N_ * DH_];   // 32MB, head-split [b,h,n,d]
__device__ float g_K[(size_t)B_ * HEADS_ * N_ * DH_];
__device__ float g_V[(size_t)B_ * HEADS_ * N_ * DH_];
__device__ float g_ctx[(size_t)M_ * H_];                // [b,n,H]
__device__ float g_y[(size_t)M_ * H_];                  // pre-LN

// ===================================================================
// Kernel 1: QKV projection. C = X @ W + b, scattered head-split.
// 128x128 tile, BK=8, 256 threads, 8x8 per-thread.
// grid: (H/128=8, M/128=64, 3)
// ===================================================================
__global__ __launch_bounds__(256) void qkv_gemm(
    const float* __restrict__ X,
    const float* __restrict__ Wq, const float* __restrict__ Wk, const float* __restrict__ Wv,
    const float* __restrict__ bq, const float* __restrict__ bk, const float* __restrict__ bv)
{
    const float* W;
    const float* bias;
    float* out;
    if (blockIdx.z == 0)      { W = Wq; bias = bq; out = g_Q; }
    else if (blockIdx.z == 1) { W = Wk; bias = bk; out = g_K; }
    else                      { W = Wv; bias = bv; out = g_V; }

    __shared__ float As[8][128];
    __shared__ float Bs[8][132];

    const int tid = threadIdx.x;
    const int m0 = blockIdx.y * 128;
    const int n0 = blockIdx.x * 128;

    const int ar = tid >> 1;              // 0..127
    const int ac = (tid & 1) * 4;         // 0 or 4
    const int br = tid >> 5;              // 0..7
    const int bc = (tid & 31) * 4;        // 0..124

    const int ty = tid >> 4, tx = tid & 15;

    float acc[8][8];
#pragma unroll
    for (int i = 0; i < 8; i++)
#pragma unroll
        for (int j = 0; j < 8; j++) acc[i][j] = 0.f;

    for (int k0 = 0; k0 < H_; k0 += 8) {
        float4 av = *(const float4*)&X[(size_t)(m0 + ar) * H_ + k0 + ac];
        float4 bv4 = *(const float4*)&W[(size_t)(k0 + br) * H_ + n0 + bc];
        As[ac + 0][ar] = av.x; As[ac + 1][ar] = av.y;
        As[ac + 2][ar] = av.z; As[ac + 3][ar] = av.w;
        *(float4*)&Bs[br][bc] = bv4;
        __syncthreads();
#pragma unroll
        for (int kk = 0; kk < 8; kk++) {
            float a[8], b[8];
            *(float4*)&a[0] = *(const float4*)&As[kk][ty * 8];
            *(float4*)&a[4] = *(const float4*)&As[kk][ty * 8 + 4];
            *(float4*)&b[0] = *(const float4*)&Bs[kk][tx * 8];
            *(float4*)&b[4] = *(const float4*)&Bs[kk][tx * 8 + 4];
#pragma unroll
            for (int i = 0; i < 8; i++)
#pragma unroll
                for (int j = 0; j < 8; j++)
                    acc[i][j] += a[i] * b[j];
        }
        __syncthreads();
    }

    // epilogue: +bias, scatter to [b, head, n, d]
    const int col0 = n0 + tx * 8;        // multiple of 8 -> all 8 cols in one head
    const int head = col0 >> 6;
    const int d0 = col0 & 63;
    float bb[8];
#pragma unroll
    for (int j = 0; j < 8; j++) bb[j] = bias[col0 + j];

#pragma unroll
    for (int i = 0; i < 8; i++) {
        const int m = m0 + ty * 8 + i;
        const int bi = m >> 10, n = m & 1023;
        float* dst = &out[(((size_t)bi * HEADS_ + head) * N_ + n) * DH_ + d0];
        float4 v0 = make_float4(acc[i][0] + bb[0], acc[i][1] + bb[1],
                                acc[i][2] + bb[2], acc[i][3] + bb[3]);
        float4 v1 = make_float4(acc[i][4] + bb[4], acc[i][5] + bb[5],
                                acc[i][6] + bb[6], acc[i][7] + bb[7]);
        *(float4*)&dst[0] = v0;
        *(float4*)&dst[4] = v1;
    }
}

// ===================================================================
// Kernel 2: flash-style attention per (b,h), q-tile=64, k-tile=64.
// grid: (N/64=16, B*HEADS=128), 256 threads, 4x4 per-thread.
// ===================================================================
#define SQ_STRIDE 65
#define SK_STRIDE 65
#define SV_STRIDE 68
#define SP_STRIDE 68
#define ATTN_SMEM ((64 * SQ_STRIDE + 64 * SK_STRIDE + 64 * SV_STRIDE + 64 * SP_STRIDE) * 4)

__global__ __launch_bounds__(256) void attn_kernel(const int* __restrict__ mask)
{
    extern __shared__ float sm[];
    float* sQ = sm;                       // [64][65]
    float* sK = sQ + 64 * SQ_STRIDE;      // [64][65]
    float* sV = sK + 64 * SK_STRIDE;      // [64][68]
    float* sP = sV + 64 * SV_STRIDE;      // [64][68]

    const int tid = threadIdx.x;
    const int bh = blockIdx.y;            // 0..127
    const int q0 = blockIdx.x * 64;
    const int b = bh >> 4;
    const int h = bh & 15;

    const float* Qg = &g_Q[(size_t)bh * N_ * DH_];
    const float* Kg = &g_K[(size_t)bh * N_ * DH_];
    const float* Vg = &g_V[(size_t)bh * N_ * DH_];

    // load Q tile
#pragma unroll
    for (int it = 0; it < 4; it++) {
        int idx = tid + it * 256;                // 0..1023 float4s
        int r = idx >> 4, c4 = (idx & 15) * 4;
        float4 v = *(const float4*)&Qg[(size_t)(q0 + r) * DH_ + c4];
        sQ[r * SQ_STRIDE + c4 + 0] = v.x;
        sQ[r * SQ_STRIDE + c4 + 1] = v.y;
        sQ[r * SQ_STRIDE + c4 + 2] = v.z;
        sQ[r * SQ_STRIDE + c4 + 3] = v.w;
    }

    const int ty = tid >> 4, tx = tid & 15;
    float m_i[4], l_i[4], o[4][4];
#pragma unroll
    for (int i = 0; i < 4; i++) {
        m_i[i] = -INFINITY; l_i[i] = 0.f;
#pragma unroll
        for (int j = 0; j < 4; j++) o[i][j] = 0.f;
    }

    for (int k0 = 0; k0 < N_; k0 += 64) {
        __syncthreads();   // previous iteration done reading sK/sV/sP
#pragma unroll
        for (int it = 0; it < 4; it++) {
            int idx = tid + it * 256;
            int r = idx >> 4, c4 = (idx & 15) * 4;
            float4 kv = *(const float4*)&Kg[(size_t)(k0 + r) * DH_ + c4];
            sK[r * SK_STRIDE + c4 + 0] = kv.x;
            sK[r * SK_STRIDE + c4 + 1] = kv.y;
            sK[r * SK_STRIDE + c4 + 2] = kv.z;
            sK[r * SK_STRIDE + c4 + 3] = kv.w;
            float4 vv = *(const float4*)&Vg[(size_t)(k0 + r) * DH_ + c4];
            *(float4*)&sV[r * SV_STRIDE + c4] = vv;
        }
        __syncthreads();

        // S = Q Kt (this thread: rows ty*4.., cols tx*4..)
        float s[4][4];
#pragma unroll
        for (int i = 0; i < 4; i++)
#pragma unroll
            for (int j = 0; j < 4; j++) s[i][j] = 0.f;

#pragma unroll 4
        for (int kd = 0; kd < 64; kd++) {
            float q[4], kk[4];
#pragma unroll
            for (int i = 0; i < 4; i++) q[i] = sQ[(ty * 4 + i) * SQ_STRIDE + kd];
#pragma unroll
            for (int j = 0; j < 4; j++) kk[j] = sK[(tx * 4 + j) * SK_STRIDE + kd];
#pragma unroll
            for (int i = 0; i < 4; i++)
#pragma unroll
                for (int j = 0; j < 4; j++)
                    s[i][j] += q[i] * kk[j];
        }

        // scale + mask
#pragma unroll
        for (int i = 0; i < 4; i++) {
            const int4 mk = *(const int4*)&mask[((size_t)b * N_ + q0 + ty * 4 + i) * N_ + k0 + tx * 4];
            s[i][0] = (mk.x != 0) ? s[i][0] * 0.125f : -1e9f;
            s[i][1] = (mk.y != 0) ? s[i][1] * 0.125f : -1e9f;
            s[i][2] = (mk.z != 0) ? s[i][2] * 0.125f : -1e9f;
            s[i][3] = (mk.w != 0) ? s[i][3] * 0.125f : -1e9f;
        }

        // online softmax update (row spread over 16 lanes)
#pragma unroll
        for (int i = 0; i < 4; i++) {
            float mt = fmaxf(fmaxf(s[i][0], s[i][1]), fmaxf(s[i][2], s[i][3]));
#pragma unroll
            for (int off = 8; off; off >>= 1)
                mt = fmaxf(mt, __shfl_xor_sync(0xffffffffu, mt, off));
            float mnew = fmaxf(m_i[i], mt);
            float rs = 0.f;
#pragma unroll
            for (int j = 0; j < 4; j++) {
                s[i][j] = __expf(s[i][j] - mnew);
                rs += s[i][j];
            }
#pragma unroll
            for (int off = 8; off; off >>= 1)
                rs += __shfl_xor_sync(0xffffffffu, rs, off);
            float alpha = __expf(m_i[i] - mnew);
            l_i[i] = l_i[i] * alpha + rs;
#pragma unroll
            for (int j = 0; j < 4; j++) o[i][j] *= alpha;
            m_i[i] = mnew;
        }

        // stage P
#pragma unroll
        for (int i = 0; i < 4; i++)
#pragma unroll
            for (int j = 0; j < 4; j++)
                sP[(ty * 4 + i) * SP_STRIDE + tx * 4 + j] = s[i][j];
        __syncthreads();

        // O += P V
#pragma unroll 4
        for (int kc = 0; kc < 64; kc++) {
            float p[4];
#pragma unroll
            for (int i = 0; i < 4; i++) p[i] = sP[(ty * 4 + i) * SP_STRIDE + kc];
            float4 v4 = *(const float4*)&sV[kc * SV_STRIDE + tx * 4];
#pragma unroll
            for (int i = 0; i < 4; i++) {
                o[i][0] += p[i] * v4.x;
                o[i][1] += p[i] * v4.y;
                o[i][2] += p[i] * v4.z;
                o[i][3] += p[i] * v4.w;
            }
        }
    }

    // finalize, write ctx [b, n, h*64 + d]
#pragma unroll
    for (int i = 0; i < 4; i++) {
        float inv = 1.f / l_i[i];
        int q = q0 + ty * 4 + i;
        float4 ov = make_float4(o[i][0] * inv, o[i][1] * inv, o[i][2] * inv, o[i][3] * inv);
        *(float4*)&g_ctx[((size_t)b * N_ + q) * H_ + h * 64 + tx * 4] = ov;
    }
}

// ===================================================================
// Kernel 3: output projection. g_y = g_ctx @ Wo + bo + hidden
// ===================================================================
__global__ __launch_bounds__(256) void out_gemm(
    const float* __restrict__ Wo, const float* __restrict__ bo,
    const float* __restrict__ hidden)
{
    __shared__ float As[8][128];
    __shared__ float Bs[8][132];

    const int tid = threadIdx.x;
    const int m0 = blockIdx.y * 128;
    const int n0 = blockIdx.x * 128;

    const int ar = tid >> 1;
    const int ac = (tid & 1) * 4;
    const int br = tid >> 5;
    const int bc = (tid & 31) * 4;
    const int ty = tid >> 4, tx = tid & 15;

    float acc[8][8];
#pragma unroll
    for (int i = 0; i < 8; i++)
#pragma unroll
        for (int j = 0; j < 8; j++) acc[i][j] = 0.f;

    for (int k0 = 0; k0 < H_; k0 += 8) {
        float4 av = *(const float4*)&g_ctx[(size_t)(m0 + ar) * H_ + k0 + ac];
        float4 bv4 = *(const float4*)&Wo[(size_t)(k0 + br) * H_ + n0 + bc];
        As[ac + 0][ar] = av.x; As[ac + 1][ar] = av.y;
        As[ac + 2][ar] = av.z; As[ac + 3][ar] = av.w;
        *(float4*)&Bs[br][bc] = bv4;
        __syncthreads();
#pragma unroll
        for (int kk = 0; kk < 8; kk++) {
            float a[8], b[8];
            *(float4*)&a[0] = *(const float4*)&As[kk][ty * 8];
            *(float4*)&a[4] = *(const float4*)&As[kk][ty * 8 + 4];
            *(float4*)&b[0] = *(const float4*)&Bs[kk][tx * 8];
            *(float4*)&b[4] = *(const float4*)&Bs[kk][tx * 8 + 4];
#pragma unroll
            for (int i = 0; i < 8; i++)
#pragma unroll
                for (int j = 0; j < 8; j++)
                    acc[i][j] += a[i] * b[j];
        }
        __syncthreads();
    }

    const int col0 = n0 + tx * 8;
    float bb[8];
#pragma unroll
    for (int j = 0; j < 8; j++) bb[j] = bo[col0 + j];

#pragma unroll
    for (int i = 0; i < 8; i++) {
        const int m = m0 + ty * 8 + i;
        const float4 h0 = *(const float4*)&hidden[(size_t)m * H_ + col0];
        const float4 h1 = *(const float4*)&hidden[(size_t)m * H_ + col0 + 4];
        float4 r0 = make_float4(acc[i][0] + bb[0] + h0.x, acc[i][1] + bb[1] + h0.y,
                                acc[i][2] + bb[2] + h0.z, acc[i][3] + bb[3] + h0.w);
        float4 r1 = make_float4(acc[i][4] + bb[4] + h1.x, acc[i][5] + bb[5] + h1.y,
                                acc[i][6] + bb[6] + h1.z, acc[i][7] + bb[7] + h1.w);
        *(float4*)&g_y[(size_t)m * H_ + col0] = r0;
        *(float4*)&g_y[(size_t)m * H_ + col0 + 4] = r1;
    }
}

// ===================================================================
// Kernel 4: LayerNorm + gather. One CTA (256 thr) per row.
// ===================================================================
__global__ __launch_bounds__(256) void ln_kernel(
    const float* __restrict__ gamma, const float* __restrict__ beta,
    const int* __restrict__ conv_len, float* __restrict__ out)
{
    const int row = blockIdx.x;           // 0..8191
    const int tid = threadIdx.x;
    const float4 v = *(const float4*)&g_y[(size_t)row * H_ + tid * 4];

    float s = v.x + v.y + v.z + v.w;
    float sq = v.x * v.x + v.y * v.y + v.z * v.z + v.w * v.w;

    __shared__ float rsum[8], rsq[8];
    const int lane = tid & 31, wid = tid >> 5;
#pragma unroll
    for (int off = 16; off; off >>= 1) {
        s += __shfl_xor_sync(0xffffffffu, s, off);
        sq += __shfl_xor_sync(0xffffffffu, sq, off);
    }
    if (lane == 0) { rsum[wid] = s; rsq[wid] = sq; }
    __syncthreads();
    if (tid == 0) {
        float a = 0.f, b2 = 0.f;
#pragma unroll
        for (int i = 0; i < 8; i++) { a += rsum[i]; b2 += rsq[i]; }
        rsum[0] = a; rsq[0] = b2;
    }
    __syncthreads();
    const float mean = rsum[0] * (1.0f / H_);
    const float var = rsq[0] * (1.0f / H_) - mean * mean;
    const float rstd = rsqrtf(var + 1e-12f);

    const float4 g = *(const float4*)&gamma[tid * 4];
    const float4 bt = *(const float4*)&beta[tid * 4];
    float4 r = make_float4((v.x - mean) * rstd * g.x + bt.x,
                           (v.y - mean) * rstd * g.y + bt.y,
                           (v.z - mean) * rstd * g.z + bt.z,
                           (v.w - mean) * rstd * g.w + bt.w);
    *(float4*)&out[(size_t)row * H_ + tid * 4] = r;

    // gather: high_emo = row base+3 (second output), perspective = base+2 (third)
    const int bi = row >> 10, n = row & 1023;
    const int base = 6 * conv_len[bi];
    if (n == base + 3)
        *(float4*)&out[CTXN_ + (size_t)bi * H_ + tid * 4] = r;
    if (n == base + 2)
        *(float4*)&out[CTXN_ + (size_t)B_ * H_ + (size_t)bi * H_ + tid * 4] = r;
}

// ===================================================================
extern "C" void kernel_launch(void* const* d_in, const int* in_sizes, int n_in,
                              void* d_out, int out_size)
{
    const float* hs        = (const float*)d_in[0];
    const int*   role_mask = (const int*)d_in[1];
    const int*   conv_len  = (const int*)d_in[2];
    const float* Wq = (const float*)d_in[3];
    const float* bq = (const float*)d_in[4];
    const float* Wk = (const float*)d_in[5];
    const float* bk = (const float*)d_in[6];
    const float* Wv = (const float*)d_in[7];
    const float* bv = (const float*)d_in[8];
    const float* Wo = (const float*)d_in[9];
    const float* bo = (const float*)d_in[10];
    const float* gamma = (const float*)d_in[11];
    const float* beta  = (const float*)d_in[12];
    float* out = (float*)d_out;

    cudaFuncSetAttribute(attn_kernel, cudaFuncAttributeMaxDynamicSharedMemorySize, ATTN_SMEM);

    qkv_gemm<<<dim3(H_ / 128, M_ / 128, 3), 256>>>(hs, Wq, Wk, Wv, bq, bk, bv);
    attn_kernel<<<dim3(N_ / 64, B_ * HEADS_), 256, ATTN_SMEM>>>(role_mask);
    out_gemm<<<dim3(H_ / 128, M_ / 128), 256>>>(Wo, bo, hs);
    ln_kernel<<<M_, 256>>>(gamma, beta, conv_len, out);
}

// round 2
// speedup vs baseline: 3.5695x; 3.5695x over previous
#include <cuda_runtime.h>
#include <math.h>
#include <stdint.h>

#define B_      8
#define N_      1024
#define H_      1024
#define HEADS_  16
#define DH_     64
#define M_      (B_ * N_)          // 8192
#define CTXN_   ((size_t)M_ * H_)  // 8388608

// -------- scratch (device globals; no allocation allowed) --------
__device__ float g_Q[(size_t)B_ * HEADS_ * N_ * DH_];   // head-split [bh][n][64]
__device__ float g_K[(size_t)B_ * HEADS_ * N_ * DH_];
__device__ float g_V[(size_t)B_ * HEADS_ * N_ * DH_];
__device__ float g_ctx[(size_t)M_ * H_];
__device__ float g_y[(size_t)M_ * H_];
__device__ unsigned g_maskbits[(size_t)B_ * N_ * (N_ / 32)];   // 1MB bitmask

// ---------------- tf32 helpers ----------------
__device__ __forceinline__ uint32_t f2tf(float x) {
    uint32_t r;
    asm("cvt.rna.tf32.f32 %0, %1;" : "=r"(r) : "f"(x));
    return r;
}

__device__ __forceinline__ void mma_tf32(float* d, const uint32_t* a, const uint32_t* b, const float* c) {
    asm volatile(
        "mma.sync.aligned.m16n8k8.row.col.f32.tf32.tf32.f32 "
        "{%0,%1,%2,%3}, {%4,%5,%6,%7}, {%8,%9}, {%10,%11,%12,%13};\n"
        : "=f"(d[0]), "=f"(d[1]), "=f"(d[2]), "=f"(d[3])
        : "r"(a[0]), "r"(a[1]), "r"(a[2]), "r"(a[3]),
          "r"(b[0]), "r"(b[1]),
          "f"(c[0]), "f"(c[1]), "f"(c[2]), "f"(c[3]));
}

// ===================================================================
// Kernel 0: pack role_mask into bitmask. one thread = one 32-bit word.
// ===================================================================
__global__ __launch_bounds__(256) void pack_mask(const int* __restrict__ mask)
{
    const int gid = blockIdx.x * 256 + threadIdx.x;      // 0 .. 262143
    const int4* p = (const int4*)(mask + (size_t)gid * 32);
    uint32_t bits = 0;
#pragma unroll
    for (int i = 0; i < 8; i++) {
        int4 v = p[i];
        bits |= (uint32_t)(v.x != 0) << (i * 4 + 0);
        bits |= (uint32_t)(v.y != 0) << (i * 4 + 1);
        bits |= (uint32_t)(v.z != 0) << (i * 4 + 2);
        bits |= (uint32_t)(v.w != 0) << (i * 4 + 3);
    }
    g_maskbits[gid] = bits;
}

// ===================================================================
// tf32 tensor-core GEMM: 128x128x16 tile, 4 warps (2x2), warp 64x64.
// MODE 0: QKV (grid.z selects W/b, scatter head-split + bias)
// MODE 1: out proj (acc + bias + residual -> g_y)
// ===================================================================
#define AS_STR 20
#define BS_STR 136

template<int MODE>
__global__ __launch_bounds__(128, 2) void gemm_tc(
    const float* __restrict__ X,
    const float* __restrict__ W0, const float* __restrict__ W1, const float* __restrict__ W2,
    const float* __restrict__ b0p, const float* __restrict__ b1p, const float* __restrict__ b2p,
    const float* __restrict__ hidden)
{
    const float* W;
    const float* bias;
    float* out;
    const float* A;
    if (MODE == 0) {
        A = X;
        if (blockIdx.z == 0)      { W = W0; bias = b0p; out = g_Q; }
        else if (blockIdx.z == 1) { W = W1; bias = b1p; out = g_K; }
        else                      { W = W2; bias = b2p; out = g_V; }
    } else {
        A = g_ctx; W = W0; bias = b0p; out = g_y;
    }

    __shared__ uint32_t As[2][128 * AS_STR];
    __shared__ uint32_t Bs[2][16 * BS_STR];

    const int tid = threadIdx.x;
    const int warp = tid >> 5, lane = tid & 31;
    const int g = lane >> 2, q = lane & 3;
    const int wm = (warp >> 1) * 64, wn = (warp & 1) * 64;
    const int m0 = blockIdx.y * 128, n0 = blockIdx.x * 128;

    float4 pa[4], pb[4];

    auto ldg_tiles = [&](int k0) {
#pragma unroll
        for (int i = 0; i < 4; i++) {
            int idx = i * 128 + tid;
            pa[i] = *(const float4*)&A[(size_t)(m0 + (idx >> 2)) * H_ + k0 + ((idx & 3) << 2)];
            pb[i] = *(const float4*)&W[(size_t)(k0 + (idx >> 5)) * H_ + n0 + ((idx & 31) << 2)];
        }
    };
    auto sts_tiles = [&](int st) {
#pragma unroll
        for (int i = 0; i < 4; i++) {
            int idx = i * 128 + tid;
            uint4 ua = make_uint4(f2tf(pa[i].x), f2tf(pa[i].y), f2tf(pa[i].z), f2tf(pa[i].w));
            *(uint4*)&As[st][(idx >> 2) * AS_STR + ((idx & 3) << 2)] = ua;
            uint4 ub = make_uint4(f2tf(pb[i].x), f2tf(pb[i].y), f2tf(pb[i].z), f2tf(pb[i].w));
            *(uint4*)&Bs[st][(idx >> 5) * BS_STR + ((idx & 31) << 2)] = ub;
        }
    };

    float acc[4][8][4];
#pragma unroll
    for (int mt = 0; mt < 4; mt++)
#pragma unroll
        for (int nt = 0; nt < 8; nt++)
#pragma unroll
            for (int j = 0; j < 4; j++) acc[mt][nt][j] = 0.f;

    ldg_tiles(0);
    sts_tiles(0);
    __syncthreads();

    for (int kt = 0; kt < 64; kt++) {
        const int cur = kt & 1;
        if (kt < 63) ldg_tiles((kt + 1) * 16);

#pragma unroll
        for (int ks = 0; ks < 2; ks++) {
            uint32_t a[4][4];
#pragma unroll
            for (int mt = 0; mt < 4; mt++) {
                const uint32_t* base = &As[cur][(wm + mt * 16 + g) * AS_STR + ks * 8 + q];
                a[mt][0] = base[0];
                a[mt][1] = base[8 * AS_STR];
                a[mt][2] = base[4];
                a[mt][3] = base[8 * AS_STR + 4];
            }
#pragma unroll
            for (int nt = 0; nt < 8; nt++) {
                uint32_t b[2];
                const uint32_t* bb = &Bs[cur][(ks * 8 + q) * BS_STR + wn + nt * 8 + g];
                b[0] = bb[0];
                b[1] = bb[4 * BS_STR];
#pragma unroll
                for (int mt = 0; mt < 4; mt++)
                    mma_tf32(acc[mt][nt], a[mt], b, acc[mt][nt]);
            }
        }
        if (kt < 63) sts_tiles(cur ^ 1);
        __syncthreads();
    }

    // ---------------- epilogue ----------------
    if (MODE == 0) {
        const int bi = m0 >> 10;
#pragma unroll
        for (int mt = 0; mt < 4; mt++) {
            const int row = m0 + wm + mt * 16 + g;
            const int n = row & 1023;
#pragma unroll
            for (int nt = 0; nt < 8; nt++) {
                const int col = n0 + wn + nt * 8 + 2 * q;
                const int head = col >> 6, d = col & 63;
                const float bb0 = __ldg(&bias[col]), bb1 = __ldg(&bias[col + 1]);
                float2 v0 = make_float2(acc[mt][nt][0] + bb0, acc[mt][nt][1] + bb1);
                float2 v1 = make_float2(acc[mt][nt][2] + bb0, acc[mt][nt][3] + bb1);
                *(float2*)&out[(((size_t)bi * HEADS_ + head) * N_ + n) * DH_ + d] = v0;
                *(float2*)&out[(((size_t)bi * HEADS_ + head) * N_ + n + 8) * DH_ + d] = v1;
            }
        }
    } else {
#pragma unroll
        for (int mt = 0; mt < 4; mt++) {
            const int row = m0 + wm + mt * 16 + g;
#pragma unroll
            for (int nt = 0; nt < 8; nt++) {
                const int col = n0 + wn + nt * 8 + 2 * q;
                const float bb0 = __ldg(&bias[col]), bb1 = __ldg(&bias[col + 1]);
                size_t o0 = (size_t)row * H_ + col;
                size_t o1 = (size_t)(row + 8) * H_ + col;
                float2 h0 = *(const float2*)&hidden[o0];
                float2 h1 = *(const float2*)&hidden[o1];
                float2 v0 = make_float2(acc[mt][nt][0] + bb0 + h0.x, acc[mt][nt][1] + bb1 + h0.y);
                float2 v1 = make_float2(acc[mt][nt][2] + bb0 + h1.x, acc[mt][nt][3] + bb1 + h1.y);
                *(float2*)&out[o0] = v0;
                *(float2*)&out[o1] = v1;
            }
        }
    }
}

// ===================================================================
// Attention: tensor-core flash attention.
// q-tile 128, key chunks 64, 4 warps (32 q-rows each), tf32 mma.
// ===================================================================
#define SQ_STR 68
#define SK_STR 68
#define SV_STR 72
#define SM_STR 33
#define SQ_OFF 0
#define SK_OFF (128 * SQ_STR)                  // 8704
#define SV_OFF (SK_OFF + 64 * SK_STR)          // 13056
#define SMK_OFF (SV_OFF + 64 * SV_STR)         // 17664
#define ATTN_SMEM_W (SMK_OFF + 128 * SM_STR)   // 21888 words
#define ATTN_SMEM_B (ATTN_SMEM_W * 4)          // 87552 bytes

__global__ __launch_bounds__(128, 2) void attn_tc()
{
    extern __shared__ uint32_t sh[];
    uint32_t* sQ = sh + SQ_OFF;
    uint32_t* sK = sh + SK_OFF;
    uint32_t* sV = sh + SV_OFF;
    uint32_t* sM = sh + SMK_OFF;

    const int tid = threadIdx.x;
    const int warp = tid >> 5, lane = tid & 31;
    const int g = lane >> 2, q = lane & 3;
    const int wm = warp * 32;

    const int bh = blockIdx.y;
    const int b = bh >> 4, h = bh & 15;
    const int q0 = blockIdx.x * 128;

    const float* Qg = g_Q + (size_t)bh * N_ * DH_;
    const float* Kg = g_K + (size_t)bh * N_ * DH_;
    const float* Vg = g_V + (size_t)bh * N_ * DH_;

    // load Q tile (128 x 64), cvt to tf32
#pragma unroll
    for (int i = 0; i < 16; i++) {
        int idx = i * 128 + tid;
        int r = idx >> 4, c4 = (idx & 15) << 2;
        float4 v = *(const float4*)&Qg[(size_t)(q0 + r) * DH_ + c4];
        *(uint4*)&sQ[r * SQ_STR + c4] = make_uint4(f2tf(v.x), f2tf(v.y), f2tf(v.z), f2tf(v.w));
    }
    // load mask bitwords for the 128 q-rows (32 words each)
#pragma unroll
    for (int i = 0; i < 32; i++) {
        int idx = i * 128 + tid;
        int r = idx >> 5, w = idx & 31;
        sM[r * SM_STR + w] = g_maskbits[((size_t)(b << 10) + q0 + r) * 32 + w];
    }

    float m_[2][2], l_[2][2], o[2][8][4];
#pragma unroll
    for (int mt = 0; mt < 2; mt++) {
        m_[mt][0] = -INFINITY; m_[mt][1] = -INFINITY;
        l_[mt][0] = 0.f; l_[mt][1] = 0.f;
#pragma unroll
        for (int dt = 0; dt < 8; dt++)
#pragma unroll
            for (int j = 0; j < 4; j++) o[mt][dt][j] = 0.f;
    }

    for (int k0 = 0; k0 < N_; k0 += 64) {
        __syncthreads();
        // load K/V chunk (64 x 64), cvt to tf32
#pragma unroll
        for (int i = 0; i < 8; i++) {
            int idx = i * 128 + tid;
            int r = idx >> 4, c4 = (idx & 15) << 2;
            float4 kv = *(const float4*)&Kg[(size_t)(k0 + r) * DH_ + c4];
            *(uint4*)&sK[r * SK_STR + c4] = make_uint4(f2tf(kv.x), f2tf(kv.y), f2tf(kv.z), f2tf(kv.w));
            float4 vv = *(const float4*)&Vg[(size_t)(k0 + r) * DH_ + c4];
            *(uint4*)&sV[r * SV_STR + c4] = make_uint4(f2tf(vv.x), f2tf(vv.y), f2tf(vv.z), f2tf(vv.w));
        }
        __syncthreads();

        // ---- S = Q K^T (32 q-rows x 64 keys per warp) ----
        float sc[2][8][4];
#pragma unroll
        for (int mt = 0; mt < 2; mt++)
#pragma unroll
            for (int nt = 0; nt < 8; nt++)
#pragma unroll
                for (int j = 0; j < 4; j++) sc[mt][nt][j] = 0.f;

#pragma unroll
        for (int ks = 0; ks < 8; ks++) {
            uint32_t a[2][4];
#pragma unroll
            for (int mt = 0; mt < 2; mt++) {
                const uint32_t* base = &sQ[(wm + mt * 16 + g) * SQ_STR + ks * 8 + q];
                a[mt][0] = base[0];
                a[mt][1] = base[8 * SQ_STR];
                a[mt][2] = base[4];
                a[mt][3] = base[8 * SQ_STR + 4];
            }
#pragma unroll
            for (int nt = 0; nt < 8; nt++) {
                uint32_t bfr[2];
                const uint32_t* kb = &sK[(nt * 8 + g) * SK_STR + ks * 8 + q];
                bfr[0] = kb[0];
                bfr[1] = kb[4];
#pragma unroll
                for (int mt = 0; mt < 2; mt++)
                    mma_tf32(sc[mt][nt], a[mt], bfr, sc[mt][nt]);
            }
        }

        // ---- mask + online softmax ----
        const int kw = k0 >> 5;
#pragma unroll
        for (int mt = 0; mt < 2; mt++) {
            const int r0 = wm + mt * 16 + g;
            const uint32_t w0a = sM[r0 * SM_STR + kw], w0b = sM[r0 * SM_STR + kw + 1];
            const uint32_t w1a = sM[(r0 + 8) * SM_STR + kw], w1b = sM[(r0 + 8) * SM_STR + kw + 1];
            float mx0 = -INFINITY, mx1 = -INFINITY;
#pragma unroll
            for (int nt = 0; nt < 8; nt++) {
                const uint32_t ws0 = (nt < 4) ? w0a : w0b;
                const uint32_t ws1 = (nt < 4) ? w1a : w1b;
                const int bb = (nt & 3) * 8 + 2 * q;
                sc[mt][nt][0] = ((ws0 >> bb) & 1u)       ? sc[mt][nt][0] * 0.125f : -1e9f;
                sc[mt][nt][1] = ((ws0 >> (bb + 1)) & 1u) ? sc[mt][nt][1] * 0.125f : -1e9f;
                sc[mt][nt][2] = ((ws1 >> bb) & 1u)       ? sc[mt][nt][2] * 0.125f : -1e9f;
                sc[mt][nt][3] = ((ws1 >> (bb + 1)) & 1u) ? sc[mt][nt][3] * 0.125f : -1e9f;
                mx0 = fmaxf(mx0, fmaxf(sc[mt][nt][0], sc[mt][nt][1]));
                mx1 = fmaxf(mx1, fmaxf(sc[mt][nt][2], sc[mt][nt][3]));
            }
            mx0 = fmaxf(mx0, __shfl_xor_sync(0xffffffffu, mx0, 1));
            mx0 = fmaxf(mx0, __shfl_xor_sync(0xffffffffu, mx0, 2));
            mx1 = fmaxf(mx1, __shfl_xor_sync(0xffffffffu, mx1, 1));
            mx1 = fmaxf(mx1, __shfl_xor_sync(0xffffffffu, mx1, 2));

            const float mn0 = fmaxf(m_[mt][0], mx0);
            const float mn1 = fmaxf(m_[mt][1], mx1);
            float sum0 = 0.f, sum1 = 0.f;
#pragma unroll
            for (int nt = 0; nt < 8; nt++) {
                sc[mt][nt][0] = __expf(sc[mt][nt][0] - mn0);
                sc[mt][nt][1] = __expf(sc[mt][nt][1] - mn0);
                sc[mt][nt][2] = __expf(sc[mt][nt][2] - mn1);
                sc[mt][nt][3] = __expf(sc[mt][nt][3] - mn1);
                sum0 += sc[mt][nt][0] + sc[mt][nt][1];
                sum1 += sc[mt][nt][2] + sc[mt][nt][3];
            }
            sum0 += __shfl_xor_sync(0xffffffffu, sum0, 1);
            sum0 += __shfl_xor_sync(0xffffffffu, sum0, 2);
            sum1 += __shfl_xor_sync(0xffffffffu, sum1, 1);
            sum1 += __shfl_xor_sync(0xffffffffu, sum1, 2);

            const float al0 = __expf(m_[mt][0] - mn0);
            const float al1 = __expf(m_[mt][1] - mn1);
            m_[mt][0] = mn0; m_[mt][1] = mn1;
            l_[mt][0] = l_[mt][0] * al0 + sum0;
            l_[mt][1] = l_[mt][1] * al1 + sum1;
#pragma unroll
            for (int dt = 0; dt < 8; dt++) {
                o[mt][dt][0] *= al0; o[mt][dt][1] *= al0;
                o[mt][dt][2] *= al1; o[mt][dt][3] *= al1;
            }
        }

        // ---- O += P V  (P frags built from S C-frags via quad shuffles) ----
        const int srcA = (lane & ~3) | (q >> 1);
        const int srcB = srcA + 2;
        const bool odd = (q & 1) != 0;
#pragma unroll
        for (int kt = 0; kt < 8; kt++) {
            uint32_t ap[2][4];
#pragma unroll
            for (int mt = 0; mt < 2; mt++) {
                const uint32_t p0 = f2tf(sc[mt][kt][0]);
                const uint32_t p1 = f2tf(sc[mt][kt][1]);
                const uint32_t p2 = f2tf(sc[mt][kt][2]);
                const uint32_t p3 = f2tf(sc[mt][kt][3]);
                const uint32_t v0a = __shfl_sync(0xffffffffu, p0, srcA);
                const uint32_t v1a = __shfl_sync(0xffffffffu, p1, srcA);
                const uint32_t v0b = __shfl_sync(0xffffffffu, p0, srcB);
                const uint32_t v1b = __shfl_sync(0xffffffffu, p1, srcB);
                const uint32_t v2a = __shfl_sync(0xffffffffu, p2, srcA);
                const uint32_t v3a = __shfl_sync(0xffffffffu, p3, srcA);
                const uint32_t v2b = __shfl_sync(0xffffffffu, p2, srcB);
                const uint32_t v3b = __shfl_sync(0xffffffffu, p3, srcB);
                ap[mt][0] = odd ? v1a : v0a;   // row g,   col q
                ap[mt][1] = odd ? v3a : v2a;   // row g+8, col q
                ap[mt][2] = odd ? v1b : v0b;   // row g,   col q+4
                ap[mt][3] = odd ? v3b : v2b;   // row g+8, col q+4
            }
#pragma unroll
            for (int dt = 0; dt < 8; dt++) {
                uint32_t vb[2];
                const uint32_t* vv = &sV[(kt * 8 + q) * SV_STR + dt * 8 + g];
                vb[0] = vv[0];
                vb[1] = vv[4 * SV_STR];
#pragma unroll
                for (int mt = 0; mt < 2; mt++)
                    mma_tf32(o[mt][dt], ap[mt], vb, o[mt][dt]);
            }
        }
    }

    // ---- epilogue: O /= l, write ctx [b,n,H] ----
#pragma unroll
    for (int mt = 0; mt < 2; mt++) {
        const float inv0 = 1.f / l_[mt][0];
        const float inv1 = 1.f / l_[mt][1];
        const int row = q0 + wm + mt * 16 + g;
#pragma unroll
        for (int dt = 0; dt < 8; dt++) {
            const int col = h * 64 + dt * 8 + 2 * q;
            float2 v0 = make_float2(o[mt][dt][0] * inv0, o[mt][dt][1] * inv0);
            float2 v1 = make_float2(o[mt][dt][2] * inv1, o[mt][dt][3] * inv1);
            *(float2*)&g_ctx[((size_t)b * N_ + row) * H_ + col] = v0;
            *(float2*)&g_ctx[((size_t)b * N_ + row + 8) * H_ + col] = v1;
        }
    }
}

// ===================================================================
// LayerNorm + gather. One CTA (256 thr) per row.
// ===================================================================
__global__ __launch_bounds__(256) void ln_kernel(
    const float* __restrict__ gamma, const float* __restrict__ beta,
    const int* __restrict__ conv_len, float* __restrict__ out)
{
    const int row = blockIdx.x;
    const int tid = threadIdx.x;
    const float4 v = *(const float4*)&g_y[(size_t)row * H_ + tid * 4];

    float s = v.x + v.y + v.z + v.w;
    float sq = v.x * v.x + v.y * v.y + v.z * v.z + v.w * v.w;

    __shared__ float rsum[8], rsq[8];
    const int lane = tid & 31, wid = tid >> 5;
#pragma unroll
    for (int off = 16; off; off >>= 1) {
        s += __shfl_xor_sync(0xffffffffu, s, off);
        sq += __shfl_xor_sync(0xffffffffu, sq, off);
    }
    if (lane == 0) { rsum[wid] = s; rsq[wid] = sq; }
    __syncthreads();
    if (tid == 0) {
        float a = 0.f, b2 = 0.f;
#pragma unroll
        for (int i = 0; i < 8; i++) { a += rsum[i]; b2 += rsq[i]; }
        rsum[0] = a; rsq[0] = b2;
    }
    __syncthreads();
    const float mean = rsum[0] * (1.0f / H_);
    const float var = rsq[0] * (1.0f / H_) - mean * mean;
    const float rstd = rsqrtf(var + 1e-12f);

    const float4 g = *(const float4*)&gamma[tid * 4];
    const float4 bt = *(const float4*)&beta[tid * 4];
    float4 r = make_float4((v.x - mean) * rstd * g.x + bt.x,
                           (v.y - mean) * rstd * g.y + bt.y,
                           (v.z - mean) * rstd * g.z + bt.z,
                           (v.w - mean) * rstd * g.w + bt.w);
    *(float4*)&out[(size_t)row * H_ + tid * 4] = r;

    const int bi = row >> 10, n = row & 1023;
    const int base = 6 * conv_len[bi];
    if (n == base + 3)
        *(float4*)&out[CTXN_ + (size_t)bi * H_ + tid * 4] = r;
    if (n == base + 2)
        *(float4*)&out[CTXN_ + (size_t)B_ * H_ + (size_t)bi * H_ + tid * 4] = r;
}

// ===================================================================
extern "C" void kernel_launch(void* const* d_in, const int* in_sizes, int n_in,
                              void* d_out, int out_size)
{
    const float* hs        = (const float*)d_in[0];
    const int*   role_mask = (const int*)d_in[1];
    const int*   conv_len  = (const int*)d_in[2];
    const float* Wq = (const float*)d_in[3];
    const float* bq = (const float*)d_in[4];
    const float* Wk = (const float*)d_in[5];
    const float* bk = (const float*)d_in[6];
    const float* Wv = (const float*)d_in[7];
    const float* bv = (const float*)d_in[8];
    const float* Wo = (const float*)d_in[9];
    const float* bo = (const float*)d_in[10];
    const float* gamma = (const float*)d_in[11];
    const float* beta  = (const float*)d_in[12];
    float* out = (float*)d_out;

    cudaFuncSetAttribute(attn_tc, cudaFuncAttributeMaxDynamicSharedMemorySize, ATTN_SMEM_B);

    pack_mask<<<(B_ * N_ * 32) / 256, 256>>>(role_mask);
    gemm_tc<0><<<dim3(H_ / 128, M_ / 128, 3), 128>>>(hs, Wq, Wk, Wv, bq, bk, bv, nullptr);
    attn_tc<<<dim3(N_ / 128, B_ * HEADS_), 128, ATTN_SMEM_B>>>();
    gemm_tc<1><<<dim3(H_ / 128, M_ / 128), 128>>>(nullptr, Wo, nullptr, nullptr, bo, nullptr, nullptr, hs);
    ln_kernel<<<M_, 256>>>(gamma, beta, conv_len, out);
}

// round 3
// speedup vs baseline: 3.5713x; 1.0005x over previous
#include <cuda_runtime.h>
#include <math.h>
#include <stdint.h>

#define B_      8
#define N_      1024
#define H_      1024
#define HEADS_  16
#define DH_     64
#define M_      (B_ * N_)          // 8192
#define CTXN_   ((size_t)M_ * H_)  // 8388608

// -------- scratch (device globals; no allocation allowed) --------
__device__ float g_Q[(size_t)B_ * HEADS_ * N_ * DH_];   // head-split [bh][n][64]
__device__ float g_K[(size_t)B_ * HEADS_ * N_ * DH_];
__device__ float g_V[(size_t)B_ * HEADS_ * N_ * DH_];
__device__ float g_ctx[(size_t)M_ * H_];
__device__ float g_y[(size_t)M_ * H_];
__device__ unsigned g_maskbits[(size_t)B_ * N_ * (N_ / 32)];   // 1MB bitmask

// ---------------- tf32 helpers ----------------
__device__ __forceinline__ uint32_t f2tf(float x) {
    uint32_t r;
    asm("cvt.rna.tf32.f32 %0, %1;" : "=r"(r) : "f"(x));
    return r;
}

__device__ __forceinline__ void mma_tf32(float* d, const uint32_t* a, const uint32_t* b, const float* c) {
    asm volatile(
        "mma.sync.aligned.m16n8k8.row.col.f32.tf32.tf32.f32 "
        "{%0,%1,%2,%3}, {%4,%5,%6,%7}, {%8,%9}, {%10,%11,%12,%13};\n"
        : "=f"(d[0]), "=f"(d[1]), "=f"(d[2]), "=f"(d[3])
        : "r"(a[0]), "r"(a[1]), "r"(a[2]), "r"(a[3]),
          "r"(b[0]), "r"(b[1]),
          "f"(c[0]), "f"(c[1]), "f"(c[2]), "f"(c[3]));
}

// ===================================================================
// Kernel 0: pack role_mask into bitmask. one thread = one 32-bit word.
// ===================================================================
__global__ __launch_bounds__(256) void pack_mask(const int* __restrict__ mask)
{
    const int gid = blockIdx.x * 256 + threadIdx.x;      // 0 .. 262143
    const int4* p = (const int4*)(mask + (size_t)gid * 32);
    uint32_t bits = 0;
#pragma unroll
    for (int i = 0; i < 8; i++) {
        int4 v = p[i];
        bits |= (uint32_t)(v.x != 0) << (i * 4 + 0);
        bits |= (uint32_t)(v.y != 0) << (i * 4 + 1);
        bits |= (uint32_t)(v.z != 0) << (i * 4 + 2);
        bits |= (uint32_t)(v.w != 0) << (i * 4 + 3);
    }
    g_maskbits[gid] = bits;
}

// ===================================================================
// tf32 tensor-core GEMM: 128x128x16 tile, 4 warps (2x2), warp 64x64.
// MODE 0: QKV (grid.z selects W/b, scatter head-split + bias)
// MODE 1: out proj (acc + bias + residual -> g_y)
// ===================================================================
#define AS_STR 20
#define BS_STR 136

template<int MODE>
__global__ __launch_bounds__(128, 2) void gemm_tc(
    const float* __restrict__ X,
    const float* __restrict__ W0, const float* __restrict__ W1, const float* __restrict__ W2,
    const float* __restrict__ b0p, const float* __restrict__ b1p, const float* __restrict__ b2p,
    const float* __restrict__ hidden)
{
    const float* W;
    const float* bias;
    float* out;
    const float* A;
    if (MODE == 0) {
        A = X;
        if (blockIdx.z == 0)      { W = W0; bias = b0p; out = g_Q; }
        else if (blockIdx.z == 1) { W = W1; bias = b1p; out = g_K; }
        else                      { W = W2; bias = b2p; out = g_V; }
    } else {
        A = g_ctx; W = W0; bias = b0p; out = g_y;
    }

    __shared__ uint32_t As[2][128 * AS_STR];
    __shared__ uint32_t Bs[2][16 * BS_STR];

    const int tid = threadIdx.x;
    const int warp = tid >> 5, lane = tid & 31;
    const int g = lane >> 2, q = lane & 3;
    const int wm = (warp >> 1) * 64, wn = (warp & 1) * 64;
    const int m0 = blockIdx.y * 128, n0 = blockIdx.x * 128;

    float4 pa[4], pb[4];

    auto ldg_tiles = [&](int k0) {
#pragma unroll
        for (int i = 0; i < 4; i++) {
            int idx = i * 128 + tid;
            pa[i] = *(const float4*)&A[(size_t)(m0 + (idx >> 2)) * H_ + k0 + ((idx & 3) << 2)];
            pb[i] = *(const float4*)&W[(size_t)(k0 + (idx >> 5)) * H_ + n0 + ((idx & 31) << 2)];
        }
    };
    auto sts_tiles = [&](int st) {
#pragma unroll
        for (int i = 0; i < 4; i++) {
            int idx = i * 128 + tid;
            uint4 ua = make_uint4(f2tf(pa[i].x), f2tf(pa[i].y), f2tf(pa[i].z), f2tf(pa[i].w));
            *(uint4*)&As[st][(idx >> 2) * AS_STR + ((idx & 3) << 2)] = ua;
            uint4 ub = make_uint4(f2tf(pb[i].x), f2tf(pb[i].y), f2tf(pb[i].z), f2tf(pb[i].w));
            *(uint4*)&Bs[st][(idx >> 5) * BS_STR + ((idx & 31) << 2)] = ub;
        }
    };

    float acc[4][8][4];
#pragma unroll
    for (int mt = 0; mt < 4; mt++)
#pragma unroll
        for (int nt = 0; nt < 8; nt++)
#pragma unroll
            for (int j = 0; j < 4; j++) acc[mt][nt][j] = 0.f;

    ldg_tiles(0);
    sts_tiles(0);
    __syncthreads();

    for (int kt = 0; kt < 64; kt++) {
        const int cur = kt & 1;
        if (kt < 63) ldg_tiles((kt + 1) * 16);

#pragma unroll
        for (int ks = 0; ks < 2; ks++) {
            uint32_t a[4][4];
#pragma unroll
            for (int mt = 0; mt < 4; mt++) {
                const uint32_t* base = &As[cur][(wm + mt * 16 + g) * AS_STR + ks * 8 + q];
                a[mt][0] = base[0];
                a[mt][1] = base[8 * AS_STR];
                a[mt][2] = base[4];
                a[mt][3] = base[8 * AS_STR + 4];
            }
#pragma unroll
            for (int nt = 0; nt < 8; nt++) {
                uint32_t b[2];
                const uint32_t* bb = &Bs[cur][(ks * 8 + q) * BS_STR + wn + nt * 8 + g];
                b[0] = bb[0];
                b[1] = bb[4 * BS_STR];
#pragma unroll
                for (int mt = 0; mt < 4; mt++)
                    mma_tf32(acc[mt][nt], a[mt], b, acc[mt][nt]);
            }
        }
        if (kt < 63) sts_tiles(cur ^ 1);
        __syncthreads();
    }

    // ---------------- epilogue ----------------
    if (MODE == 0) {
        const int bi = m0 >> 10;
#pragma unroll
        for (int mt = 0; mt < 4; mt++) {
            const int row = m0 + wm + mt * 16 + g;
            const int n = row & 1023;
#pragma unroll
            for (int nt = 0; nt < 8; nt++) {
                const int col = n0 + wn + nt * 8 + 2 * q;
                const int head = col >> 6, d = col & 63;
                const float bb0 = __ldg(&bias[col]), bb1 = __ldg(&bias[col + 1]);
                float2 v0 = make_float2(acc[mt][nt][0] + bb0, acc[mt][nt][1] + bb1);
                float2 v1 = make_float2(acc[mt][nt][2] + bb0, acc[mt][nt][3] + bb1);
                *(float2*)&out[(((size_t)bi * HEADS_ + head) * N_ + n) * DH_ + d] = v0;
                *(float2*)&out[(((size_t)bi * HEADS_ + head) * N_ + n + 8) * DH_ + d] = v1;
            }
        }
    } else {
#pragma unroll
        for (int mt = 0; mt < 4; mt++) {
            const int row = m0 + wm + mt * 16 + g;
#pragma unroll
            for (int nt = 0; nt < 8; nt++) {
                const int col = n0 + wn + nt * 8 + 2 * q;
                const float bb0 = __ldg(&bias[col]), bb1 = __ldg(&bias[col + 1]);
                size_t o0 = (size_t)row * H_ + col;
                size_t o1 = (size_t)(row + 8) * H_ + col;
                float2 h0 = *(const float2*)&hidden[o0];
                float2 h1 = *(const float2*)&hidden[o1];
                float2 v0 = make_float2(acc[mt][nt][0] + bb0 + h0.x, acc[mt][nt][1] + bb1 + h0.y);
                float2 v1 = make_float2(acc[mt][nt][2] + bb0 + h1.x, acc[mt][nt][3] + bb1 + h1.y);
                *(float2*)&out[o0] = v0;
                *(float2*)&out[o1] = v1;
            }
        }
    }
}

// ===================================================================
// Attention: tensor-core flash attention.
// q-tile 128, key chunks 64, 4 warps (32 q-rows each), tf32 mma.
// ===================================================================
#define SQ_STR 68
#define SK_STR 68
#define SV_STR 72
#define SM_STR 33
#define SQ_OFF 0
#define SK_OFF (128 * SQ_STR)                  // 8704
#define SV_OFF (SK_OFF + 64 * SK_STR)          // 13056
#define SMK_OFF (SV_OFF + 64 * SV_STR)         // 17664
#define ATTN_SMEM_W (SMK_OFF + 128 * SM_STR)   // 21888 words
#define ATTN_SMEM_B (ATTN_SMEM_W * 4)          // 87552 bytes

__global__ __launch_bounds__(128, 2) void attn_tc()
{
    extern __shared__ uint32_t sh[];
    uint32_t* sQ = sh + SQ_OFF;
    uint32_t* sK = sh + SK_OFF;
    uint32_t* sV = sh + SV_OFF;
    uint32_t* sM = sh + SMK_OFF;

    const int tid = threadIdx.x;
    const int warp = tid >> 5, lane = tid & 31;
    const int g = lane >> 2, q = lane & 3;
    const int wm = warp * 32;

    const int bh = blockIdx.y;
    const int b = bh >> 4, h = bh & 15;
    const int q0 = blockIdx.x * 128;

    const float* Qg = g_Q + (size_t)bh * N_ * DH_;
    const float* Kg = g_K + (size_t)bh * N_ * DH_;
    const float* Vg = g_V + (size_t)bh * N_ * DH_;

    // load Q tile (128 x 64), cvt to tf32
#pragma unroll
    for (int i = 0; i < 16; i++) {
        int idx = i * 128 + tid;
        int r = idx >> 4, c4 = (idx & 15) << 2;
        float4 v = *(const float4*)&Qg[(size_t)(q0 + r) * DH_ + c4];
        *(uint4*)&sQ[r * SQ_STR + c4] = make_uint4(f2tf(v.x), f2tf(v.y), f2tf(v.z), f2tf(v.w));
    }
    // load mask bitwords for the 128 q-rows (32 words each)
#pragma unroll
    for (int i = 0; i < 32; i++) {
        int idx = i * 128 + tid;
        int r = idx >> 5, w = idx & 31;
        sM[r * SM_STR + w] = g_maskbits[((size_t)(b << 10) + q0 + r) * 32 + w];
    }

    float m_[2][2], l_[2][2], o[2][8][4];
#pragma unroll
    for (int mt = 0; mt < 2; mt++) {
        m_[mt][0] = -INFINITY; m_[mt][1] = -INFINITY;
        l_[mt][0] = 0.f; l_[mt][1] = 0.f;
#pragma unroll
        for (int dt = 0; dt < 8; dt++)
#pragma unroll
            for (int j = 0; j < 4; j++) o[mt][dt][j] = 0.f;
    }

    for (int k0 = 0; k0 < N_; k0 += 64) {
        __syncthreads();
        // load K/V chunk (64 x 64), cvt to tf32
#pragma unroll
        for (int i = 0; i < 8; i++) {
            int idx = i * 128 + tid;
            int r = idx >> 4, c4 = (idx & 15) << 2;
            float4 kv = *(const float4*)&Kg[(size_t)(k0 + r) * DH_ + c4];
            *(uint4*)&sK[r * SK_STR + c4] = make_uint4(f2tf(kv.x), f2tf(kv.y), f2tf(kv.z), f2tf(kv.w));
            float4 vv = *(const float4*)&Vg[(size_t)(k0 + r) * DH_ + c4];
            *(uint4*)&sV[r * SV_STR + c4] = make_uint4(f2tf(vv.x), f2tf(vv.y), f2tf(vv.z), f2tf(vv.w));
        }
        __syncthreads();

        // ---- S = Q K^T (32 q-rows x 64 keys per warp) ----
        float sc[2][8][4];
#pragma unroll
        for (int mt = 0; mt < 2; mt++)
#pragma unroll
            for (int nt = 0; nt < 8; nt++)
#pragma unroll
                for (int j = 0; j < 4; j++) sc[mt][nt][j] = 0.f;

#pragma unroll
        for (int ks = 0; ks < 8; ks++) {
            uint32_t a[2][4];
#pragma unroll
            for (int mt = 0; mt < 2; mt++) {
                const uint32_t* base = &sQ[(wm + mt * 16 + g) * SQ_STR + ks * 8 + q];
                a[mt][0] = base[0];
                a[mt][1] = base[8 * SQ_STR];
                a[mt][2] = base[4];
                a[mt][3] = base[8 * SQ_STR + 4];
            }
#pragma unroll
            for (int nt = 0; nt < 8; nt++) {
                uint32_t bfr[2];
                const uint32_t* kb = &sK[(nt * 8 + g) * SK_STR + ks * 8 + q];
                bfr[0] = kb[0];
                bfr[1] = kb[4];
#pragma unroll
                for (int mt = 0; mt < 2; mt++)
                    mma_tf32(sc[mt][nt], a[mt], bfr, sc[mt][nt]);
            }
        }

        // ---- mask + online softmax ----
        const int kw = k0 >> 5;
#pragma unroll
        for (int mt = 0; mt < 2; mt++) {
            const int r0 = wm + mt * 16 + g;
            const uint32_t w0a = sM[r0 * SM_STR + kw], w0b = sM[r0 * SM_STR + kw + 1];
            const uint32_t w1a = sM[(r0 + 8) * SM_STR + kw], w1b = sM[(r0 + 8) * SM_STR + kw + 1];
            float mx0 = -INFINITY, mx1 = -INFINITY;
#pragma unroll
            for (int nt = 0; nt < 8; nt++) {
                const uint32_t ws0 = (nt < 4) ? w0a : w0b;
                const uint32_t ws1 = (nt < 4) ? w1a : w1b;
                const int bb = (nt & 3) * 8 + 2 * q;
                sc[mt][nt][0] = ((ws0 >> bb) & 1u)       ? sc[mt][nt][0] * 0.125f : -1e9f;
                sc[mt][nt][1] = ((ws0 >> (bb + 1)) & 1u) ? sc[mt][nt][1] * 0.125f : -1e9f;
                sc[mt][nt][2] = ((ws1 >> bb) & 1u)       ? sc[mt][nt][2] * 0.125f : -1e9f;
                sc[mt][nt][3] = ((ws1 >> (bb + 1)) & 1u) ? sc[mt][nt][3] * 0.125f : -1e9f;
                mx0 = fmaxf(mx0, fmaxf(sc[mt][nt][0], sc[mt][nt][1]));
                mx1 = fmaxf(mx1, fmaxf(sc[mt][nt][2], sc[mt][nt][3]));
            }
            mx0 = fmaxf(mx0, __shfl_xor_sync(0xffffffffu, mx0, 1));
            mx0 = fmaxf(mx0, __shfl_xor_sync(0xffffffffu, mx0, 2));
            mx1 = fmaxf(mx1, __shfl_xor_sync(0xffffffffu, mx1, 1));
            mx1 = fmaxf(mx1, __shfl_xor_sync(0xffffffffu, mx1, 2));

            const float mn0 = fmaxf(m_[mt][0], mx0);
            const float mn1 = fmaxf(m_[mt][1], mx1);
            float sum0 = 0.f, sum1 = 0.f;
#pragma unroll
            for (int nt = 0; nt < 8; nt++) {
                sc[mt][nt][0] = __expf(sc[mt][nt][0] - mn0);
                sc[mt][nt][1] = __expf(sc[mt][nt][1] - mn0);
                sc[mt][nt][2] = __expf(sc[mt][nt][2] - mn1);
                sc[mt][nt][3] = __expf(sc[mt][nt][3] - mn1);
                sum0 += sc[mt][nt][0] + sc[mt][nt][1];
                sum1 += sc[mt][nt][2] + sc[mt][nt][3];
            }
            sum0 += __shfl_xor_sync(0xffffffffu, sum0, 1);
            sum0 += __shfl_xor_sync(0xffffffffu, sum0, 2);
            sum1 += __shfl_xor_sync(0xffffffffu, sum1, 1);
            sum1 += __shfl_xor_sync(0xffffffffu, sum1, 2);

            const float al0 = __expf(m_[mt][0] - mn0);
            const float al1 = __expf(m_[mt][1] - mn1);
            m_[mt][0] = mn0; m_[mt][1] = mn1;
            l_[mt][0] = l_[mt][0] * al0 + sum0;
            l_[mt][1] = l_[mt][1] * al1 + sum1;
#pragma unroll
            for (int dt = 0; dt < 8; dt++) {
                o[mt][dt][0] *= al0; o[mt][dt][1] *= al0;
                o[mt][dt][2] *= al1; o[mt][dt][3] *= al1;
            }
        }

        // ---- O += P V  (P frags built from S C-frags via quad shuffles) ----
        const int srcA = (lane & ~3) | (q >> 1);
        const int srcB = srcA + 2;
        const bool odd = (q & 1) != 0;
#pragma unroll
        for (int kt = 0; kt < 8; kt++) {
            uint32_t ap[2][4];
#pragma unroll
            for (int mt = 0; mt < 2; mt++) {
                const uint32_t p0 = f2tf(sc[mt][kt][0]);
                const uint32_t p1 = f2tf(sc[mt][kt][1]);
                const uint32_t p2 = f2tf(sc[mt][kt][2]);
                const uint32_t p3 = f2tf(sc[mt][kt][3]);
                const uint32_t v0a = __shfl_sync(0xffffffffu, p0, srcA);
                const uint32_t v1a = __shfl_sync(0xffffffffu, p1, srcA);
                const uint32_t v0b = __shfl_sync(0xffffffffu, p0, srcB);
                const uint32_t v1b = __shfl_sync(0xffffffffu, p1, srcB);
                const uint32_t v2a = __shfl_sync(0xffffffffu, p2, srcA);
                const uint32_t v3a = __shfl_sync(0xffffffffu, p3, srcA);
                const uint32_t v2b = __shfl_sync(0xffffffffu, p2, srcB);
                const uint32_t v3b = __shfl_sync(0xffffffffu, p3, srcB);
                ap[mt][0] = odd ? v1a : v0a;   // row g,   col q
                ap[mt][1] = odd ? v3a : v2a;   // row g+8, col q
                ap[mt][2] = odd ? v1b : v0b;   // row g,   col q+4
                ap[mt][3] = odd ? v3b : v2b;   // row g+8, col q+4
            }
#pragma unroll
            for (int dt = 0; dt < 8; dt++) {
                uint32_t vb[2];
                const uint32_t* vv = &sV[(kt * 8 + q) * SV_STR + dt * 8 + g];
                vb[0] = vv[0];
                vb[1] = vv[4 * SV_STR];
#pragma unroll
                for (int mt = 0; mt < 2; mt++)
                    mma_tf32(o[mt][dt], ap[mt], vb, o[mt][dt]);
            }
        }
    }

    // ---- epilogue: O /= l, write ctx [b,n,H] ----
#pragma unroll
    for (int mt = 0; mt < 2; mt++) {
        const float inv0 = 1.f / l_[mt][0];
        const float inv1 = 1.f / l_[mt][1];
        const int row = q0 + wm + mt * 16 + g;
#pragma unroll
        for (int dt = 0; dt < 8; dt++) {
            const int col = h * 64 + dt * 8 + 2 * q;
            float2 v0 = make_float2(o[mt][dt][0] * inv0, o[mt][dt][1] * inv0);
            float2 v1 = make_float2(o[mt][dt][2] * inv1, o[mt][dt][3] * inv1);
            *(float2*)&g_ctx[((size_t)b * N_ + row) * H_ + col] = v0;
            *(float2*)&g_ctx[((size_t)b * N_ + row + 8) * H_ + col] = v1;
        }
    }
}

// ===================================================================
// LayerNorm + gather. One CTA (256 thr) per row.
// ===================================================================
__global__ __launch_bounds__(256) void ln_kernel(
    const float* __restrict__ gamma, const float* __restrict__ beta,
    const int* __restrict__ conv_len, float* __restrict__ out)
{
    const int row = blockIdx.x;
    const int tid = threadIdx.x;
    const float4 v = *(const float4*)&g_y[(size_t)row * H_ + tid * 4];

    float s = v.x + v.y + v.z + v.w;
    float sq = v.x * v.x + v.y * v.y + v.z * v.z + v.w * v.w;

    __shared__ float rsum[8], rsq[8];
    const int lane = tid & 31, wid = tid >> 5;
#pragma unroll
    for (int off = 16; off; off >>= 1) {
        s += __shfl_xor_sync(0xffffffffu, s, off);
        sq += __shfl_xor_sync(0xffffffffu, sq, off);
    }
    if (lane == 0) { rsum[wid] = s; rsq[wid] = sq; }
    __syncthreads();
    if (tid == 0) {
        float a = 0.f, b2 = 0.f;
#pragma unroll
        for (int i = 0; i < 8; i++) { a += rsum[i]; b2 += rsq[i]; }
        rsum[0] = a; rsq[0] = b2;
    }
    __syncthreads();
    const float mean = rsum[0] * (1.0f / H_);
    const float var = rsq[0] * (1.0f / H_) - mean * mean;
    const float rstd = rsqrtf(var + 1e-12f);

    const float4 g = *(const float4*)&gamma[tid * 4];
    const float4 bt = *(const float4*)&beta[tid * 4];
    float4 r = make_float4((v.x - mean) * rstd * g.x + bt.x,
                           (v.y - mean) * rstd * g.y + bt.y,
                           (v.z - mean) * rstd * g.z + bt.z,
                           (v.w - mean) * rstd * g.w + bt.w);
    *(float4*)&out[(size_t)row * H_ + tid * 4] = r;

    const int bi = row >> 10, n = row & 1023;
    const int base = 6 * conv_len[bi];
    if (n == base + 3)
        *(float4*)&out[CTXN_ + (size_t)bi * H_ + tid * 4] = r;
    if (n == base + 2)
        *(float4*)&out[CTXN_ + (size_t)B_ * H_ + (size_t)bi * H_ + tid * 4] = r;
}

// ===================================================================
extern "C" void kernel_launch(void* const* d_in, const int* in_sizes, int n_in,
                              void* d_out, int out_size)
{
    const float* hs        = (const float*)d_in[0];
    const int*   role_mask = (const int*)d_in[1];
    const int*   conv_len  = (const int*)d_in[2];
    const float* Wq = (const float*)d_in[3];
    const float* bq = (const float*)d_in[4];
    const float* Wk = (const float*)d_in[5];
    const float* bk = (const float*)d_in[6];
    const float* Wv = (const float*)d_in[7];
    const float* bv = (const float*)d_in[8];
    const float* Wo = (const float*)d_in[9];
    const float* bo = (const float*)d_in[10];
    const float* gamma = (const float*)d_in[11];
    const float* beta  = (const float*)d_in[12];
    float* out = (float*)d_out;

    cudaFuncSetAttribute(attn_tc, cudaFuncAttributeMaxDynamicSharedMemorySize, ATTN_SMEM_B);

    pack_mask<<<(B_ * N_ * 32) / 256, 256>>>(role_mask);
    gemm_tc<0><<<dim3(H_ / 128, M_ / 128, 3), 128>>>(hs, Wq, Wk, Wv, bq, bk, bv, nullptr);
    attn_tc<<<dim3(N_ / 128, B_ * HEADS_), 128, ATTN_SMEM_B>>>();
    gemm_tc<1><<<dim3(H_ / 128, M_ / 128), 128>>>(nullptr, Wo, nullptr, nullptr, bo, nullptr, nullptr, hs);
    ln_kernel<<<M_, 256>>>(gamma, beta, conv_len, out);
}

// round 4
// speedup vs baseline: 3.5825x; 1.0031x over previous
#include <cuda_runtime.h>
#include <math.h>
#include <stdint.h>

#define B_      8
#define N_      1024
#define H_      1024
#define HEADS_  16
#define DH_     64
#define M_      (B_ * N_)          // 8192
#define CTXN_   ((size_t)M_ * H_)  // 8388608

// -------- scratch (device globals; no allocation allowed) --------
__device__ float g_Q[(size_t)B_ * HEADS_ * N_ * DH_];   // head-split [bh][n][64]
__device__ float g_K[(size_t)B_ * HEADS_ * N_ * DH_];
__device__ float g_V[(size_t)B_ * HEADS_ * N_ * DH_];
__device__ float g_ctx[(size_t)M_ * H_];
__device__ float g_y[(size_t)M_ * H_];
__device__ unsigned g_maskbits[(size_t)B_ * N_ * (N_ / 32)];   // 1MB bitmask

// ---------------- tf32 helpers ----------------
__device__ __forceinline__ uint32_t f2tf(float x) {
    uint32_t r;
    asm("cvt.rna.tf32.f32 %0, %1;" : "=r"(r) : "f"(x));
    return r;
}

__device__ __forceinline__ void mma_tf32(float* d, const uint32_t* a, const uint32_t* b, const float* c) {
    asm volatile(
        "mma.sync.aligned.m16n8k8.row.col.f32.tf32.tf32.f32 "
        "{%0,%1,%2,%3}, {%4,%5,%6,%7}, {%8,%9}, {%10,%11,%12,%13};\n"
        : "=f"(d[0]), "=f"(d[1]), "=f"(d[2]), "=f"(d[3])
        : "r"(a[0]), "r"(a[1]), "r"(a[2]), "r"(a[3]),
          "r"(b[0]), "r"(b[1]),
          "f"(c[0]), "f"(c[1]), "f"(c[2]), "f"(c[3]));
}

// ===================================================================
// Kernel 0: pack role_mask into bitmask. one thread = one 32-bit word.
// ===================================================================
__global__ __launch_bounds__(256) void pack_mask(const int* __restrict__ mask)
{
    const int gid = blockIdx.x * 256 + threadIdx.x;      // 0 .. 262143
    const int4* p = (const int4*)(mask + (size_t)gid * 32);
    uint32_t bits = 0;
#pragma unroll
    for (int i = 0; i < 8; i++) {
        int4 v = p[i];
        bits |= (uint32_t)(v.x != 0) << (i * 4 + 0);
        bits |= (uint32_t)(v.y != 0) << (i * 4 + 1);
        bits |= (uint32_t)(v.z != 0) << (i * 4 + 2);
        bits |= (uint32_t)(v.w != 0) << (i * 4 + 3);
    }
    g_maskbits[gid] = bits;
}

// ===================================================================
// tf32 tensor-core GEMM: 128x128x16 tile, 4 warps (2x2), warp 64x64.
// MODE 0: QKV (grid.z selects W/b, scatter head-split + bias)
// MODE 1: out proj (acc + bias + residual -> g_y)
// ===================================================================
#define AS_STR 20
#define BS_STR 136

template<int MODE>
__global__ __launch_bounds__(128, 2) void gemm_tc(
    const float* __restrict__ X,
    const float* __restrict__ W0, const float* __restrict__ W1, const float* __restrict__ W2,
    const float* __restrict__ b0p, const float* __restrict__ b1p, const float* __restrict__ b2p,
    const float* __restrict__ hidden)
{
    const float* W;
    const float* bias;
    float* out;
    const float* A;
    if (MODE == 0) {
        A = X;
        if (blockIdx.z == 0)      { W = W0; bias = b0p; out = g_Q; }
        else if (blockIdx.z == 1) { W = W1; bias = b1p; out = g_K; }
        else                      { W = W2; bias = b2p; out = g_V; }
    } else {
        A = g_ctx; W = W0; bias = b0p; out = g_y;
    }

    __shared__ uint32_t As[2][128 * AS_STR];
    __shared__ uint32_t Bs[2][16 * BS_STR];

    const int tid = threadIdx.x;
    const int warp = tid >> 5, lane = tid & 31;
    const int g = lane >> 2, q = lane & 3;
    const int wm = (warp >> 1) * 64, wn = (warp & 1) * 64;
    const int m0 = blockIdx.y * 128, n0 = blockIdx.x * 128;

    float4 pa[4], pb[4];

    auto ldg_tiles = [&](int k0) {
#pragma unroll
        for (int i = 0; i < 4; i++) {
            int idx = i * 128 + tid;
            pa[i] = *(const float4*)&A[(size_t)(m0 + (idx >> 2)) * H_ + k0 + ((idx & 3) << 2)];
            pb[i] = *(const float4*)&W[(size_t)(k0 + (idx >> 5)) * H_ + n0 + ((idx & 31) << 2)];
        }
    };
    auto sts_tiles = [&](int st) {
#pragma unroll
        for (int i = 0; i < 4; i++) {
            int idx = i * 128 + tid;
            uint4 ua = make_uint4(f2tf(pa[i].x), f2tf(pa[i].y), f2tf(pa[i].z), f2tf(pa[i].w));
            *(uint4*)&As[st][(idx >> 2) * AS_STR + ((idx & 3) << 2)] = ua;
            uint4 ub = make_uint4(f2tf(pb[i].x), f2tf(pb[i].y), f2tf(pb[i].z), f2tf(pb[i].w));
            *(uint4*)&Bs[st][(idx >> 5) * BS_STR + ((idx & 31) << 2)] = ub;
        }
    };

    float acc[4][8][4];
#pragma unroll
    for (int mt = 0; mt < 4; mt++)
#pragma unroll
        for (int nt = 0; nt < 8; nt++)
#pragma unroll
            for (int j = 0; j < 4; j++) acc[mt][nt][j] = 0.f;

    ldg_tiles(0);
    sts_tiles(0);
    __syncthreads();

    for (int kt = 0; kt < 64; kt++) {
        const int cur = kt & 1;
        if (kt < 63) ldg_tiles((kt + 1) * 16);

#pragma unroll
        for (int ks = 0; ks < 2; ks++) {
            uint32_t a[4][4];
#pragma unroll
            for (int mt = 0; mt < 4; mt++) {
                const uint32_t* base = &As[cur][(wm + mt * 16 + g) * AS_STR + ks * 8 + q];
                a[mt][0] = base[0];
                a[mt][1] = base[8 * AS_STR];
                a[mt][2] = base[4];
                a[mt][3] = base[8 * AS_STR + 4];
            }
#pragma unroll
            for (int nt = 0; nt < 8; nt++) {
                uint32_t b[2];
                const uint32_t* bb = &Bs[cur][(ks * 8 + q) * BS_STR + wn + nt * 8 + g];
                b[0] = bb[0];
                b[1] = bb[4 * BS_STR];
#pragma unroll
                for (int mt = 0; mt < 4; mt++)
                    mma_tf32(acc[mt][nt], a[mt], b, acc[mt][nt]);
            }
        }
        if (kt < 63) sts_tiles(cur ^ 1);
        __syncthreads();
    }

    // ---------------- epilogue ----------------
    if (MODE == 0) {
        const int bi = m0 >> 10;
#pragma unroll
        for (int mt = 0; mt < 4; mt++) {
            const int row = m0 + wm + mt * 16 + g;
            const int n = row & 1023;
#pragma unroll
            for (int nt = 0; nt < 8; nt++) {
                const int col = n0 + wn + nt * 8 + 2 * q;
                const int head = col >> 6, d = col & 63;
                const float bb0 = __ldg(&bias[col]), bb1 = __ldg(&bias[col + 1]);
                float2 v0 = make_float2(acc[mt][nt][0] + bb0, acc[mt][nt][1] + bb1);
                float2 v1 = make_float2(acc[mt][nt][2] + bb0, acc[mt][nt][3] + bb1);
                *(float2*)&out[(((size_t)bi * HEADS_ + head) * N_ + n) * DH_ + d] = v0;
                *(float2*)&out[(((size_t)bi * HEADS_ + head) * N_ + n + 8) * DH_ + d] = v1;
            }
        }
    } else {
#pragma unroll
        for (int mt = 0; mt < 4; mt++) {
            const int row = m0 + wm + mt * 16 + g;
#pragma unroll
            for (int nt = 0; nt < 8; nt++) {
                const int col = n0 + wn + nt * 8 + 2 * q;
                const float bb0 = __ldg(&bias[col]), bb1 = __ldg(&bias[col + 1]);
                size_t o0 = (size_t)row * H_ + col;
                size_t o1 = (size_t)(row + 8) * H_ + col;
                float2 h0 = *(const float2*)&hidden[o0];
                float2 h1 = *(const float2*)&hidden[o1];
                float2 v0 = make_float2(acc[mt][nt][0] + bb0 + h0.x, acc[mt][nt][1] + bb1 + h0.y);
                float2 v1 = make_float2(acc[mt][nt][2] + bb0 + h1.x, acc[mt][nt][3] + bb1 + h1.y);
                *(float2*)&out[o0] = v0;
                *(float2*)&out[o1] = v1;
            }
        }
    }
}

// ===================================================================
// Attention: tensor-core flash attention.
// q-tile 128, key chunks 64, 4 warps (32 q-rows each), tf32 mma.
// ===================================================================
#define SQ_STR 68
#define SK_STR 68
#define SV_STR 72
#define SM_STR 33
#define SQ_OFF 0
#define SK_OFF (128 * SQ_STR)                  // 8704
#define SV_OFF (SK_OFF + 64 * SK_STR)          // 13056
#define SMK_OFF (SV_OFF + 64 * SV_STR)         // 17664
#define ATTN_SMEM_W (SMK_OFF + 128 * SM_STR)   // 21888 words
#define ATTN_SMEM_B (ATTN_SMEM_W * 4)          // 87552 bytes

__global__ __launch_bounds__(128, 2) void attn_tc()
{
    extern __shared__ uint32_t sh[];
    uint32_t* sQ = sh + SQ_OFF;
    uint32_t* sK = sh + SK_OFF;
    uint32_t* sV = sh + SV_OFF;
    uint32_t* sM = sh + SMK_OFF;

    const int tid = threadIdx.x;
    const int warp = tid >> 5, lane = tid & 31;
    const int g = lane >> 2, q = lane & 3;
    const int wm = warp * 32;

    const int bh = blockIdx.y;
    const int b = bh >> 4, h = bh & 15;
    const int q0 = blockIdx.x * 128;

    const float* Qg = g_Q + (size_t)bh * N_ * DH_;
    const float* Kg = g_K + (size_t)bh * N_ * DH_;
    const float* Vg = g_V + (size_t)bh * N_ * DH_;

    // load Q tile (128 x 64), cvt to tf32
#pragma unroll
    for (int i = 0; i < 16; i++) {
        int idx = i * 128 + tid;
        int r = idx >> 4, c4 = (idx & 15) << 2;
        float4 v = *(const float4*)&Qg[(size_t)(q0 + r) * DH_ + c4];
        *(uint4*)&sQ[r * SQ_STR + c4] = make_uint4(f2tf(v.x), f2tf(v.y), f2tf(v.z), f2tf(v.w));
    }
    // load mask bitwords for the 128 q-rows (32 words each)
#pragma unroll
    for (int i = 0; i < 32; i++) {
        int idx = i * 128 + tid;
        int r = idx >> 5, w = idx & 31;
        sM[r * SM_STR + w] = g_maskbits[((size_t)(b << 10) + q0 + r) * 32 + w];
    }

    float m_[2][2], l_[2][2], o[2][8][4];
#pragma unroll
    for (int mt = 0; mt < 2; mt++) {
        m_[mt][0] = -INFINITY; m_[mt][1] = -INFINITY;
        l_[mt][0] = 0.f; l_[mt][1] = 0.f;
#pragma unroll
        for (int dt = 0; dt < 8; dt++)
#pragma unroll
            for (int j = 0; j < 4; j++) o[mt][dt][j] = 0.f;
    }

    for (int k0 = 0; k0 < N_; k0 += 64) {
        __syncthreads();
        // load K/V chunk (64 x 64), cvt to tf32
#pragma unroll
        for (int i = 0; i < 8; i++) {
            int idx = i * 128 + tid;
            int r = idx >> 4, c4 = (idx & 15) << 2;
            float4 kv = *(const float4*)&Kg[(size_t)(k0 + r) * DH_ + c4];
            *(uint4*)&sK[r * SK_STR + c4] = make_uint4(f2tf(kv.x), f2tf(kv.y), f2tf(kv.z), f2tf(kv.w));
            float4 vv = *(const float4*)&Vg[(size_t)(k0 + r) * DH_ + c4];
            *(uint4*)&sV[r * SV_STR + c4] = make_uint4(f2tf(vv.x), f2tf(vv.y), f2tf(vv.z), f2tf(vv.w));
        }
        __syncthreads();

        // ---- S = Q K^T (32 q-rows x 64 keys per warp) ----
        float sc[2][8][4];
#pragma unroll
        for (int mt = 0; mt < 2; mt++)
#pragma unroll
            for (int nt = 0; nt < 8; nt++)
#pragma unroll
                for (int j = 0; j < 4; j++) sc[mt][nt][j] = 0.f;

#pragma unroll
        for (int ks = 0; ks < 8; ks++) {
            uint32_t a[2][4];
#pragma unroll
            for (int mt = 0; mt < 2; mt++) {
                const uint32_t* base = &sQ[(wm + mt * 16 + g) * SQ_STR + ks * 8 + q];
                a[mt][0] = base[0];
                a[mt][1] = base[8 * SQ_STR];
                a[mt][2] = base[4];
                a[mt][3] = base[8 * SQ_STR + 4];
            }
#pragma unroll
            for (int nt = 0; nt < 8; nt++) {
                uint32_t bfr[2];
                const uint32_t* kb = &sK[(nt * 8 + g) * SK_STR + ks * 8 + q];
                bfr[0] = kb[0];
                bfr[1] = kb[4];
#pragma unroll
                for (int mt = 0; mt < 2; mt++)
                    mma_tf32(sc[mt][nt], a[mt], bfr, sc[mt][nt]);
            }
        }

        // ---- mask + online softmax ----
        const int kw = k0 >> 5;
#pragma unroll
        for (int mt = 0; mt < 2; mt++) {
            const int r0 = wm + mt * 16 + g;
            const uint32_t w0a = sM[r0 * SM_STR + kw], w0b = sM[r0 * SM_STR + kw + 1];
            const uint32_t w1a = sM[(r0 + 8) * SM_STR + kw], w1b = sM[(r0 + 8) * SM_STR + kw + 1];
            float mx0 = -INFINITY, mx1 = -INFINITY;
#pragma unroll
            for (int nt = 0; nt < 8; nt++) {
                const uint32_t ws0 = (nt < 4) ? w0a : w0b;
                const uint32_t ws1 = (nt < 4) ? w1a : w1b;
                const int bb = (nt & 3) * 8 + 2 * q;
                sc[mt][nt][0] = ((ws0 >> bb) & 1u)       ? sc[mt][nt][0] * 0.125f : -1e9f;
                sc[mt][nt][1] = ((ws0 >> (bb + 1)) & 1u) ? sc[mt][nt][1] * 0.125f : -1e9f;
                sc[mt][nt][2] = ((ws1 >> bb) & 1u)       ? sc[mt][nt][2] * 0.125f : -1e9f;
                sc[mt][nt][3] = ((ws1 >> (bb + 1)) & 1u) ? sc[mt][nt][3] * 0.125f : -1e9f;
                mx0 = fmaxf(mx0, fmaxf(sc[mt][nt][0], sc[mt][nt][1]));
                mx1 = fmaxf(mx1, fmaxf(sc[mt][nt][2], sc[mt][nt][3]));
            }
            mx0 = fmaxf(mx0, __shfl_xor_sync(0xffffffffu, mx0, 1));
            mx0 = fmaxf(mx0, __shfl_xor_sync(0xffffffffu, mx0, 2));
            mx1 = fmaxf(mx1, __shfl_xor_sync(0xffffffffu, mx1, 1));
            mx1 = fmaxf(mx1, __shfl_xor_sync(0xffffffffu, mx1, 2));

            const float mn0 = fmaxf(m_[mt][0], mx0);
            const float mn1 = fmaxf(m_[mt][1], mx1);
            float sum0 = 0.f, sum1 = 0.f;
#pragma unroll
            for (int nt = 0; nt < 8; nt++) {
                sc[mt][nt][0] = __expf(sc[mt][nt][0] - mn0);
                sc[mt][nt][1] = __expf(sc[mt][nt][1] - mn0);
                sc[mt][nt][2] = __expf(sc[mt][nt][2] - mn1);
                sc[mt][nt][3] = __expf(sc[mt][nt][3] - mn1);
                sum0 += sc[mt][nt][0] + sc[mt][nt][1];
                sum1 += sc[mt][nt][2] + sc[mt][nt][3];
            }
            sum0 += __shfl_xor_sync(0xffffffffu, sum0, 1);
            sum0 += __shfl_xor_sync(0xffffffffu, sum0, 2);
            sum1 += __shfl_xor_sync(0xffffffffu, sum1, 1);
            sum1 += __shfl_xor_sync(0xffffffffu, sum1, 2);

            const float al0 = __expf(m_[mt][0] - mn0);
            const float al1 = __expf(m_[mt][1] - mn1);
            m_[mt][0] = mn0; m_[mt][1] = mn1;
            l_[mt][0] = l_[mt][0] * al0 + sum0;
            l_[mt][1] = l_[mt][1] * al1 + sum1;
#pragma unroll
            for (int dt = 0; dt < 8; dt++) {
                o[mt][dt][0] *= al0; o[mt][dt][1] *= al0;
                o[mt][dt][2] *= al1; o[mt][dt][3] *= al1;
            }
        }

        // ---- O += P V  (P frags built from S C-frags via quad shuffles) ----
        const int srcA = (lane & ~3) | (q >> 1);
        const int srcB = srcA + 2;
        const bool odd = (q & 1) != 0;
#pragma unroll
        for (int kt = 0; kt < 8; kt++) {
            uint32_t ap[2][4];
#pragma unroll
            for (int mt = 0; mt < 2; mt++) {
                const uint32_t p0 = f2tf(sc[mt][kt][0]);
                const uint32_t p1 = f2tf(sc[mt][kt][1]);
                const uint32_t p2 = f2tf(sc[mt][kt][2]);
                const uint32_t p3 = f2tf(sc[mt][kt][3]);
                const uint32_t v0a = __shfl_sync(0xffffffffu, p0, srcA);
                const uint32_t v1a = __shfl_sync(0xffffffffu, p1, srcA);
                const uint32_t v0b = __shfl_sync(0xffffffffu, p0, srcB);
                const uint32_t v1b = __shfl_sync(0xffffffffu, p1, srcB);
                const uint32_t v2a = __shfl_sync(0xffffffffu, p2, srcA);
                const uint32_t v3a = __shfl_sync(0xffffffffu, p3, srcA);
                const uint32_t v2b = __shfl_sync(0xffffffffu, p2, srcB);
                const uint32_t v3b = __shfl_sync(0xffffffffu, p3, srcB);
                ap[mt][0] = odd ? v1a : v0a;   // row g,   col q
                ap[mt][1] = odd ? v3a : v2a;   // row g+8, col q
                ap[mt][2] = odd ? v1b : v0b;   // row g,   col q+4
                ap[mt][3] = odd ? v3b : v2b;   // row g+8, col q+4
            }
#pragma unroll
            for (int dt = 0; dt < 8; dt++) {
                uint32_t vb[2];
                const uint32_t* vv = &sV[(kt * 8 + q) * SV_STR + dt * 8 + g];
                vb[0] = vv[0];
                vb[1] = vv[4 * SV_STR];
#pragma unroll
                for (int mt = 0; mt < 2; mt++)
                    mma_tf32(o[mt][dt], ap[mt], vb, o[mt][dt]);
            }
        }
    }

    // ---- epilogue: O /= l, write ctx [b,n,H] ----
#pragma unroll
    for (int mt = 0; mt < 2; mt++) {
        const float inv0 = 1.f / l_[mt][0];
        const float inv1 = 1.f / l_[mt][1];
        const int row = q0 + wm + mt * 16 + g;
#pragma unroll
        for (int dt = 0; dt < 8; dt++) {
            const int col = h * 64 + dt * 8 + 2 * q;
            float2 v0 = make_float2(o[mt][dt][0] * inv0, o[mt][dt][1] * inv0);
            float2 v1 = make_float2(o[mt][dt][2] * inv1, o[mt][dt][3] * inv1);
            *(float2*)&g_ctx[((size_t)b * N_ + row) * H_ + col] = v0;
            *(float2*)&g_ctx[((size_t)b * N_ + row + 8) * H_ + col] = v1;
        }
    }
}

// ===================================================================
// LayerNorm + gather. One CTA (256 thr) per row.
// ===================================================================
__global__ __launch_bounds__(256) void ln_kernel(
    const float* __restrict__ gamma, const float* __restrict__ beta,
    const int* __restrict__ conv_len, float* __restrict__ out)
{
    const int row = blockIdx.x;
    const int tid = threadIdx.x;
    const float4 v = *(const float4*)&g_y[(size_t)row * H_ + tid * 4];

    float s = v.x + v.y + v.z + v.w;
    float sq = v.x * v.x + v.y * v.y + v.z * v.z + v.w * v.w;

    __shared__ float rsum[8], rsq[8];
    const int lane = tid & 31, wid = tid >> 5;
#pragma unroll
    for (int off = 16; off; off >>= 1) {
        s += __shfl_xor_sync(0xffffffffu, s, off);
        sq += __shfl_xor_sync(0xffffffffu, sq, off);
    }
    if (lane == 0) { rsum[wid] = s; rsq[wid] = sq; }
    __syncthreads();
    if (tid == 0) {
        float a = 0.f, b2 = 0.f;
#pragma unroll
        for (int i = 0; i < 8; i++) { a += rsum[i]; b2 += rsq[i]; }
        rsum[0] = a; rsq[0] = b2;
    }
    __syncthreads();
    const float mean = rsum[0] * (1.0f / H_);
    const float var = rsq[0] * (1.0f / H_) - mean * mean;
    const float rstd = rsqrtf(var + 1e-12f);

    const float4 g = *(const float4*)&gamma[tid * 4];
    const float4 bt = *(const float4*)&beta[tid * 4];
    float4 r = make_float4((v.x - mean) * rstd * g.x + bt.x,
                           (v.y - mean) * rstd * g.y + bt.y,
                           (v.z - mean) * rstd * g.z + bt.z,
                           (v.w - mean) * rstd * g.w + bt.w);
    *(float4*)&out[(size_t)row * H_ + tid * 4] = r;

    const int bi = row >> 10, n = row & 1023;
    const int base = 6 * conv_len[bi];
    if (n == base + 3)
        *(float4*)&out[CTXN_ + (size_t)bi * H_ + tid * 4] = r;
    if (n == base + 2)
        *(float4*)&out[CTXN_ + (size_t)B_ * H_ + (size_t)bi * H_ + tid * 4] = r;
}

// ===================================================================
extern "C" void kernel_launch(void* const* d_in, const int* in_sizes, int n_in,
                              void* d_out, int out_size)
{
    const float* hs        = (const float*)d_in[0];
    const int*   role_mask = (const int*)d_in[1];
    const int*   conv_len  = (const int*)d_in[2];
    const float* Wq = (const float*)d_in[3];
    const float* bq = (const float*)d_in[4];
    const float* Wk = (const float*)d_in[5];
    const float* bk = (const float*)d_in[6];
    const float* Wv = (const float*)d_in[7];
    const float* bv = (const float*)d_in[8];
    const float* Wo = (const float*)d_in[9];
    const float* bo = (const float*)d_in[10];
    const float* gamma = (const float*)d_in[11];
    const float* beta  = (const float*)d_in[12];
    float* out = (float*)d_out;

    cudaFuncSetAttribute(attn_tc, cudaFuncAttributeMaxDynamicSharedMemorySize, ATTN_SMEM_B);

    pack_mask<<<(B_ * N_ * 32) / 256, 256>>>(role_mask);
    gemm_tc<0><<<dim3(H_ / 128, M_ / 128, 3), 128>>>(hs, Wq, Wk, Wv, bq, bk, bv, nullptr);
    attn_tc<<<dim3(N_ / 128, B_ * HEADS_), 128, ATTN_SMEM_B>>>();
    gemm_tc<1><<<dim3(H_ / 128, M_ / 128), 128>>>(nullptr, Wo, nullptr, nullptr, bo, nullptr, nullptr, hs);
    ln_kernel<<<M_, 256>>>(gamma, beta, conv_len, out);
}